// round 14
// baseline (speedup 1.0000x reference)
#include <cuda_runtime.h>
#include <cuda_bf16.h>
#include <cstdint>

#define NN 100000
#define EE 1600000
#define DD 128
#define NBLK ((NN + 1023) / 1024)

// ---------------- scratch (device globals; no allocs allowed) ----------------
__device__ float g_msg[(size_t)NN * DD];     // mean-aggregated messages
__device__ float g_h  [(size_t)NN * DD];     // layer-0 activations
__device__ int   g_rowptr[NN + 1];
__device__ int   g_colidx[EE];
__device__ int   g_hist[NN];
__device__ int   g_bsum[NBLK];
__device__ int   g_ei_is64;

// ---------------- edge-index dtype detection ----------------
__global__ void detect_kernel(const int* __restrict__ ei_words) {
    if (threadIdx.x == 0 && blockIdx.x == 0) {
        int is64 = 1;
        for (int i = 1; i < 256; i += 2) {
            if (ei_words[i] != 0) { is64 = 0; break; }
        }
        g_ei_is64 = is64;
    }
}
__device__ __forceinline__ int load_edge(const void* ei, size_t idx) {
    if (g_ei_is64) return (int)((const long long*)ei)[idx];
    return ((const int*)ei)[idx];
}

// ---------------- CSR build ----------------
__global__ void zero_hist_kernel(int N) {
    int i = blockIdx.x * blockDim.x + threadIdx.x;
    if (i < N) g_hist[i] = 0;
}
__global__ void hist_kernel(const void* __restrict__ ei, int E) {
    int e = blockIdx.x * blockDim.x + threadIdx.x;
    if (e >= E) return;
    atomicAdd(&g_hist[load_edge(ei, (size_t)E + e)], 1);
}
__global__ __launch_bounds__(1024)
void scan1_kernel(int N) {
    __shared__ int s[1024];
    int gi = blockIdx.x * 1024 + threadIdx.x;
    int v = (gi < N) ? g_hist[gi] : 0;
    s[threadIdx.x] = v;
    __syncthreads();
    int x = v;
#pragma unroll
    for (int off = 1; off < 1024; off <<= 1) {
        int t = (threadIdx.x >= off) ? s[threadIdx.x - off] : 0;
        __syncthreads();
        x += t;
        s[threadIdx.x] = x;
        __syncthreads();
    }
    if (gi <= N) g_rowptr[gi] = x - v;
    if (threadIdx.x == 1023) g_bsum[blockIdx.x] = x;
}
__global__ void scan2_kernel(int nblk) {
    if (threadIdx.x == 0 && blockIdx.x == 0) {
        int run = 0;
        for (int b = 0; b < nblk; b++) { int t = g_bsum[b]; g_bsum[b] = run; run += t; }
    }
}
__global__ void scan3_kernel(int N, int E) {
    int i = blockIdx.x * blockDim.x + threadIdx.x;
    if (i < N) {
        g_rowptr[i] += g_bsum[i >> 10];
        g_hist[i] = 0;
    }
    if (i == 0) g_rowptr[N] = E;
}
__global__ void scatter_kernel(const void* __restrict__ ei, int E) {
    int e = blockIdx.x * blockDim.x + threadIdx.x;
    if (e >= E) return;
    int s = load_edge(ei, e);
    int d = load_edge(ei, (size_t)E + e);
    int p = g_rowptr[d] + atomicAdd(&g_hist[d], 1);
    g_colidx[p] = s;
}

// ---------------- gather aggregation: one warp per dst node ----------------
__global__ __launch_bounds__(256)
void gather_agg_kernel(const float* __restrict__ feat_in, int N) {
    const float* feat = feat_in ? feat_in : g_h;
    int node = (blockIdx.x * blockDim.x + threadIdx.x) >> 5;
    int lane = threadIdx.x & 31;
    if (node >= N) return;

    int beg = g_rowptr[node];
    int end = g_rowptr[node + 1];
    const float4* f4 = reinterpret_cast<const float4*>(feat);
    float4 acc = make_float4(0.f, 0.f, 0.f, 0.f);

    int e = beg;
    for (; e + 4 <= end; e += 4) {
        int s0 = g_colidx[e], s1 = g_colidx[e + 1], s2 = g_colidx[e + 2], s3 = g_colidx[e + 3];
        float4 a = f4[(size_t)s0 * 32 + lane];
        float4 b = f4[(size_t)s1 * 32 + lane];
        float4 c = f4[(size_t)s2 * 32 + lane];
        float4 d = f4[(size_t)s3 * 32 + lane];
        acc.x += (a.x + b.x) + (c.x + d.x);
        acc.y += (a.y + b.y) + (c.y + d.y);
        acc.z += (a.z + b.z) + (c.z + d.z);
        acc.w += (a.w + b.w) + (c.w + d.w);
    }
    for (; e < end; e++) {
        float4 a = f4[(size_t)g_colidx[e] * 32 + lane];
        acc.x += a.x; acc.y += a.y; acc.z += a.z; acc.w += a.w;
    }
    float r = 1.f / fmaxf((float)(end - beg), 1.f);
    acc.x *= r; acc.y *= r; acc.z *= r; acc.w *= r;
    reinterpret_cast<float4*>(g_msg)[(size_t)node * 32 + lane] = acc;
}

// ---------------- fused SAGE layer GEMM (R12 inner loop + register double-buffer) ----------------
// OUT[n][c] = act( sum_k g_msg[n][k]*Wl[k][c] + X[n][k]*Wr[k][c] + B[c] )
#define S_BM 64
#define S_BK 16
template <bool RELU>
__global__ __launch_bounds__(256)
void sage_kernel(const float* __restrict__ X_in,
                 const float* __restrict__ Wl,
                 const float* __restrict__ Wr,
                 const float* __restrict__ B,
                 float* __restrict__ OUT_in,
                 int N) {
    const float* X = X_in ? X_in : g_h;
    float* OUT     = OUT_in ? OUT_in : g_h;

    __shared__ float sAx[S_BM][S_BK];
    __shared__ float sAm[S_BM][S_BK];
    __shared__ float sBl[S_BK][128];
    __shared__ float sBr[S_BK][128];

    const int tid = threadIdx.x;
    const int tx  = tid & 31;
    const int ty  = tid >> 5;
    const int bm  = blockIdx.x * S_BM;

    // A staging coords (4 elems per src per thread)
    const int ar = tid >> 4;          // row 0..15 base; +16 each iter via idx formula
    // B staging coords (8 elems per src per thread)
    // idx = tid + i*256 -> kk = idx>>7, c = idx&127

    float acc[8][4];
#pragma unroll
    for (int i = 0; i < 8; i++)
#pragma unroll
        for (int j = 0; j < 4; j++) acc[i][j] = 0.f;

    // staging registers
    float rAx[4], rAm[4], rBl[8], rBr[8];

    // ---- prefetch chunk 0 ----
#pragma unroll
    for (int i = 0; i < 4; i++) {
        int idx = tid + i * 256;
        int r = idx >> 4, c = idx & 15;
        int n = bm + r;
        rAx[i] = 0.f; rAm[i] = 0.f;
        if (n < N) {
            rAx[i] = X[(size_t)n * DD + c];
            rAm[i] = g_msg[(size_t)n * DD + c];
        }
    }
#pragma unroll
    for (int i = 0; i < 8; i++) {
        int idx = tid + i * 256;
        int kk = idx >> 7, c = idx & 127;
        rBl[i] = Wl[(size_t)kk * 128 + c];
        rBr[i] = Wr[(size_t)kk * 128 + c];
    }

    for (int kc = 0; kc < DD; kc += S_BK) {
        // store staged regs -> smem
#pragma unroll
        for (int i = 0; i < 4; i++) {
            int idx = tid + i * 256;
            int r = idx >> 4, c = idx & 15;
            sAx[r][c] = rAx[i];
            sAm[r][c] = rAm[i];
        }
#pragma unroll
        for (int i = 0; i < 8; i++) {
            int idx = tid + i * 256;
            int kk = idx >> 7, c = idx & 127;
            sBl[kk][c] = rBl[i];
            sBr[kk][c] = rBr[i];
        }
        __syncthreads();

        // prefetch next chunk into regs (overlaps with compute below)
        int kn = kc + S_BK;
        if (kn < DD) {
#pragma unroll
            for (int i = 0; i < 4; i++) {
                int idx = tid + i * 256;
                int r = idx >> 4, c = idx & 15;
                int n = bm + r;
                rAx[i] = 0.f; rAm[i] = 0.f;
                if (n < N) {
                    rAx[i] = X[(size_t)n * DD + kn + c];
                    rAm[i] = g_msg[(size_t)n * DD + kn + c];
                }
            }
#pragma unroll
            for (int i = 0; i < 8; i++) {
                int idx = tid + i * 256;
                int kk = idx >> 7, c = idx & 127;
                rBl[i] = Wl[(size_t)(kn + kk) * 128 + c];
                rBr[i] = Wr[(size_t)(kn + kk) * 128 + c];
            }
        }

        // compute (identical to R12 inner loop)
#pragma unroll
        for (int kk = 0; kk < S_BK; kk++) {
            float4 bl = *reinterpret_cast<const float4*>(&sBl[kk][tx * 4]);
            float4 br = *reinterpret_cast<const float4*>(&sBr[kk][tx * 4]);
#pragma unroll
            for (int i = 0; i < 8; i++) {
                float am = sAm[ty * 8 + i][kk];
                float ax = sAx[ty * 8 + i][kk];
                acc[i][0] += am * bl.x + ax * br.x;
                acc[i][1] += am * bl.y + ax * br.y;
                acc[i][2] += am * bl.z + ax * br.z;
                acc[i][3] += am * bl.w + ax * br.w;
            }
        }
        __syncthreads();
    }

    float4 bias = *reinterpret_cast<const float4*>(&B[tx * 4]);
#pragma unroll
    for (int i = 0; i < 8; i++) {
        int n = bm + ty * 8 + i;
        if (n < N) {
            float4 o;
            o.x = acc[i][0] + bias.x;
            o.y = acc[i][1] + bias.y;
            o.z = acc[i][2] + bias.z;
            o.w = acc[i][3] + bias.w;
            if (RELU) {
                o.x = fmaxf(o.x, 0.f); o.y = fmaxf(o.y, 0.f);
                o.z = fmaxf(o.z, 0.f); o.w = fmaxf(o.w, 0.f);
            }
            *reinterpret_cast<float4*>(&OUT[(size_t)n * DD + tx * 4]) = o;
        }
    }
}

// ---------------- fused MLP + pred ----------------
// h1 = relu( relu(EMB) @ Wm1 + bm1 );  PRED[n] = h1[n] . Wm2 + bm2
#define M_BM 32
#define M_BK 32
__global__ __launch_bounds__(256)
void mlp_pred_kernel(const float* __restrict__ EMB,
                     const float* __restrict__ Wm1,
                     const float* __restrict__ bm1,
                     const float* __restrict__ Wm2,
                     const float* __restrict__ bm2,
                     float* __restrict__ PRED,
                     int N) {
    __shared__ float sA[M_BM][M_BK];
    __shared__ float sB[M_BK][256];
    __shared__ float sred[M_BM][65];

    const int tid = threadIdx.x;
    const int tx  = tid & 63;
    const int ty  = tid >> 6;
    const int bm  = blockIdx.x * M_BM;

    float acc[8][4];
#pragma unroll
    for (int i = 0; i < 8; i++)
#pragma unroll
        for (int j = 0; j < 4; j++) acc[i][j] = 0.f;

    for (int kc = 0; kc < DD; kc += M_BK) {
#pragma unroll
        for (int i = 0; i < 4; i++) {
            int idx = tid + i * 256;
            int r = idx >> 5, c = idx & 31;
            int n = bm + r;
            sA[r][c] = (n < N) ? fmaxf(EMB[(size_t)n * DD + kc + c], 0.f) : 0.f;
        }
#pragma unroll
        for (int i = 0; i < 32; i++) {
            int idx = tid + i * 256;
            int kk = idx >> 8, c = idx & 255;
            sB[kk][c] = Wm1[(size_t)(kc + kk) * 256 + c];
        }
        __syncthreads();

#pragma unroll
        for (int kk = 0; kk < M_BK; kk++) {
            float4 b4 = *reinterpret_cast<const float4*>(&sB[kk][tx * 4]);
#pragma unroll
            for (int i = 0; i < 8; i++) {
                float a = sA[ty * 8 + i][kk];
                acc[i][0] += a * b4.x;
                acc[i][1] += a * b4.y;
                acc[i][2] += a * b4.z;
                acc[i][3] += a * b4.w;
            }
        }
        __syncthreads();
    }

    float4 bias = *reinterpret_cast<const float4*>(&bm1[tx * 4]);
    float4 w2   = *reinterpret_cast<const float4*>(&Wm2[tx * 4]);
#pragma unroll
    for (int i = 0; i < 8; i++) {
        float h0 = fmaxf(acc[i][0] + bias.x, 0.f);
        float h1 = fmaxf(acc[i][1] + bias.y, 0.f);
        float h2 = fmaxf(acc[i][2] + bias.z, 0.f);
        float h3 = fmaxf(acc[i][3] + bias.w, 0.f);
        sred[ty * 8 + i][tx] = h0 * w2.x + h1 * w2.y + h2 * w2.z + h3 * w2.w;
    }
    __syncthreads();

    if (tid < M_BM) {
        int n = bm + tid;
        if (n < N) {
            float s = 0.f;
#pragma unroll
            for (int j = 0; j < 64; j++) s += sred[tid][j];
            PRED[n] = s + bm2[0];
        }
    }
}

// ---------------- launcher ----------------
extern "C" void kernel_launch(void* const* d_in, const int* in_sizes, int n_in,
                              void* d_out, int out_size) {
    const float* x   = (const float*)d_in[0];
    const void*  ei  = d_in[1];
    const float* Wl0 = (const float*)d_in[2];
    const float* b0  = (const float*)d_in[3];
    const float* Wr0 = (const float*)d_in[4];
    const float* Wl1 = (const float*)d_in[5];
    const float* b1  = (const float*)d_in[6];
    const float* Wr1 = (const float*)d_in[7];
    const float* Wm1 = (const float*)d_in[8];
    const float* bm1 = (const float*)d_in[9];
    const float* Wm2 = (const float*)d_in[10];
    const float* bm2 = (const float*)d_in[11];

    const int N = in_sizes[0] / DD;
    const int E = in_sizes[1] / 2;

    float* out  = (float*)d_out;
    float* emb  = out;                       // [N,128]
    float* pred = out + (size_t)N * DD;      // [N,1]

    const int egrid = (E + 255) / 256;
    const int ngrid = (N + 255) / 256;
    const int nblk  = (N + 1023) / 1024;
    const int ggrid = (N + 7) / 8;
    const int sgrid = (N + S_BM - 1) / S_BM;
    const int mgrid = (N + M_BM - 1) / M_BM;

    detect_kernel<<<1, 32>>>((const int*)ei);

    // ---- CSR build (once; reused by both layers) ----
    zero_hist_kernel<<<ngrid, 256>>>(N);
    hist_kernel<<<egrid, 256>>>(ei, E);
    scan1_kernel<<<nblk, 1024>>>(N);
    scan2_kernel<<<1, 32>>>(nblk);
    scan3_kernel<<<ngrid, 256>>>(N, E);
    scatter_kernel<<<egrid, 256>>>(ei, E);

    // ---- layer 0 ----
    gather_agg_kernel<<<ggrid, 256>>>(x, N);
    sage_kernel<true><<<sgrid, 256>>>(x, Wl0, Wr0, b0, nullptr, N);   // OUT -> g_h

    // ---- layer 1 (emb -> d_out) ----
    gather_agg_kernel<<<ggrid, 256>>>(nullptr, N);
    sage_kernel<false><<<sgrid, 256>>>(nullptr, Wl1, Wr1, b1, emb, N);

    // ---- post-mp MLP + pred (fused) ----
    mlp_pred_kernel<<<mgrid, 256>>>(emb, Wm1, bm1, Wm2, bm2, pred, N);
}

// round 15
// speedup vs baseline: 1.1373x; 1.1373x over previous
#include <cuda_runtime.h>
#include <cuda_bf16.h>
#include <cstdint>

#define NN 100000
#define EE 1600000
#define DD 128
#define NBLK ((NN + 1023) / 1024)

// ---------------- scratch (device globals; no allocs allowed) ----------------
__device__ float g_msg[(size_t)NN * DD];     // mean-aggregated messages
__device__ float g_h  [(size_t)NN * DD];     // layer-0 activations
__device__ int   g_rowptr[NN + 1];
__device__ int   g_colidx[EE];
__device__ int   g_hist[NN];
__device__ int   g_bsum[NBLK];
__device__ int   g_ei_is64;

// ---------------- edge-index dtype detection ----------------
__global__ void detect_kernel(const int* __restrict__ ei_words) {
    if (threadIdx.x == 0 && blockIdx.x == 0) {
        int is64 = 1;
        for (int i = 1; i < 256; i += 2) {
            if (ei_words[i] != 0) { is64 = 0; break; }
        }
        g_ei_is64 = is64;
    }
}
__device__ __forceinline__ int load_edge(const void* ei, size_t idx) {
    if (g_ei_is64) return (int)((const long long*)ei)[idx];
    return ((const int*)ei)[idx];
}

// ---------------- CSR build ----------------
__global__ void zero_hist_kernel(int N) {
    int i = blockIdx.x * blockDim.x + threadIdx.x;
    if (i < N) g_hist[i] = 0;
}
__global__ void hist_kernel(const void* __restrict__ ei, int E) {
    int e = blockIdx.x * blockDim.x + threadIdx.x;
    if (e >= E) return;
    atomicAdd(&g_hist[load_edge(ei, (size_t)E + e)], 1);
}
__global__ __launch_bounds__(1024)
void scan1_kernel(int N) {
    __shared__ int s[1024];
    int gi = blockIdx.x * 1024 + threadIdx.x;
    int v = (gi < N) ? g_hist[gi] : 0;
    s[threadIdx.x] = v;
    __syncthreads();
    int x = v;
#pragma unroll
    for (int off = 1; off < 1024; off <<= 1) {
        int t = (threadIdx.x >= off) ? s[threadIdx.x - off] : 0;
        __syncthreads();
        x += t;
        s[threadIdx.x] = x;
        __syncthreads();
    }
    if (gi <= N) g_rowptr[gi] = x - v;
    if (threadIdx.x == 1023) g_bsum[blockIdx.x] = x;
}
__global__ void scan2_kernel(int nblk) {
    if (threadIdx.x == 0 && blockIdx.x == 0) {
        int run = 0;
        for (int b = 0; b < nblk; b++) { int t = g_bsum[b]; g_bsum[b] = run; run += t; }
    }
}
__global__ void scan3_kernel(int N, int E) {
    int i = blockIdx.x * blockDim.x + threadIdx.x;
    if (i < N) {
        g_rowptr[i] += g_bsum[i >> 10];
        g_hist[i] = 0;
    }
    if (i == 0) g_rowptr[N] = E;
}
__global__ void scatter_kernel(const void* __restrict__ ei, int E) {
    int e = blockIdx.x * blockDim.x + threadIdx.x;
    if (e >= E) return;
    int s = load_edge(ei, e);
    int d = load_edge(ei, (size_t)E + e);
    int p = g_rowptr[d] + atomicAdd(&g_hist[d], 1);
    g_colidx[p] = s;
}

// ---------------- gather aggregation: one warp per dst node ----------------
__global__ __launch_bounds__(256)
void gather_agg_kernel(const float* __restrict__ feat_in, int N) {
    const float* feat = feat_in ? feat_in : g_h;
    int node = (blockIdx.x * blockDim.x + threadIdx.x) >> 5;
    int lane = threadIdx.x & 31;
    if (node >= N) return;

    int beg = g_rowptr[node];
    int end = g_rowptr[node + 1];
    const float4* f4 = reinterpret_cast<const float4*>(feat);
    float4 acc = make_float4(0.f, 0.f, 0.f, 0.f);

    int e = beg;
    for (; e + 4 <= end; e += 4) {
        int s0 = g_colidx[e], s1 = g_colidx[e + 1], s2 = g_colidx[e + 2], s3 = g_colidx[e + 3];
        float4 a = f4[(size_t)s0 * 32 + lane];
        float4 b = f4[(size_t)s1 * 32 + lane];
        float4 c = f4[(size_t)s2 * 32 + lane];
        float4 d = f4[(size_t)s3 * 32 + lane];
        acc.x += (a.x + b.x) + (c.x + d.x);
        acc.y += (a.y + b.y) + (c.y + d.y);
        acc.z += (a.z + b.z) + (c.z + d.z);
        acc.w += (a.w + b.w) + (c.w + d.w);
    }
    for (; e < end; e++) {
        float4 a = f4[(size_t)g_colidx[e] * 32 + lane];
        acc.x += a.x; acc.y += a.y; acc.z += a.z; acc.w += a.w;
    }
    float r = 1.f / fmaxf((float)(end - beg), 1.f);
    acc.x *= r; acc.y *= r; acc.z *= r; acc.w *= r;
    reinterpret_cast<float4*>(g_msg)[(size_t)node * 32 + lane] = acc;
}

// ---------------- fused SAGE layer GEMM (R12 inner loop, float4 staging) ----------------
// OUT[n][c] = act( sum_k g_msg[n][k]*Wl[k][c] + X[n][k]*Wr[k][c] + B[c] )
#define S_BM 64
#define S_BK 16
template <bool RELU>
__global__ __launch_bounds__(256)
void sage_kernel(const float* __restrict__ X_in,
                 const float* __restrict__ Wl,
                 const float* __restrict__ Wr,
                 const float* __restrict__ B,
                 float* __restrict__ OUT_in,
                 int N) {
    const float* X = X_in ? X_in : g_h;
    float* OUT     = OUT_in ? OUT_in : g_h;

    __shared__ __align__(16) float sAx[S_BM][S_BK];
    __shared__ __align__(16) float sAm[S_BM][S_BK];
    __shared__ __align__(16) float sBl[S_BK][128];
    __shared__ __align__(16) float sBr[S_BK][128];

    const int tid = threadIdx.x;
    const int tx  = tid & 31;
    const int ty  = tid >> 5;
    const int bm  = blockIdx.x * S_BM;

    // A staging: 64 rows x 16 cols = 256 float4s -> 1 float4 per thread per source
    const int a_r = tid >> 2;          // row 0..63
    const int a_q = (tid & 3) * 4;     // col 0,4,8,12
    // B staging: 16 rows x 128 cols = 512 float4s -> 2 float4 per thread per matrix
    //   idx = tid + i*256 -> kk = idx>>5, c = (idx&31)*4

    float acc[8][4];
#pragma unroll
    for (int i = 0; i < 8; i++)
#pragma unroll
        for (int j = 0; j < 4; j++) acc[i][j] = 0.f;

    for (int kc = 0; kc < DD; kc += S_BK) {
        // A tiles: one float4 per source per thread
        {
            int n = bm + a_r;
            float4 vx = make_float4(0.f, 0.f, 0.f, 0.f);
            float4 vm = vx;
            if (n < N) {
                vx = *reinterpret_cast<const float4*>(X + (size_t)n * DD + kc + a_q);
                vm = *reinterpret_cast<const float4*>(g_msg + (size_t)n * DD + kc + a_q);
            }
            *reinterpret_cast<float4*>(&sAx[a_r][a_q]) = vx;
            *reinterpret_cast<float4*>(&sAm[a_r][a_q]) = vm;
        }
        // B tiles: two float4 per matrix per thread
#pragma unroll
        for (int i = 0; i < 2; i++) {
            int idx = tid + i * 256;
            int kk = idx >> 5, c = (idx & 31) * 4;
            *reinterpret_cast<float4*>(&sBl[kk][c]) =
                *reinterpret_cast<const float4*>(Wl + (size_t)(kc + kk) * 128 + c);
            *reinterpret_cast<float4*>(&sBr[kk][c]) =
                *reinterpret_cast<const float4*>(Wr + (size_t)(kc + kk) * 128 + c);
        }
        __syncthreads();

#pragma unroll
        for (int kk = 0; kk < S_BK; kk++) {
            float4 bl = *reinterpret_cast<const float4*>(&sBl[kk][tx * 4]);
            float4 br = *reinterpret_cast<const float4*>(&sBr[kk][tx * 4]);
#pragma unroll
            for (int i = 0; i < 8; i++) {
                float am = sAm[ty * 8 + i][kk];
                float ax = sAx[ty * 8 + i][kk];
                acc[i][0] += am * bl.x + ax * br.x;
                acc[i][1] += am * bl.y + ax * br.y;
                acc[i][2] += am * bl.z + ax * br.z;
                acc[i][3] += am * bl.w + ax * br.w;
            }
        }
        __syncthreads();
    }

    float4 bias = *reinterpret_cast<const float4*>(&B[tx * 4]);
#pragma unroll
    for (int i = 0; i < 8; i++) {
        int n = bm + ty * 8 + i;
        if (n < N) {
            float4 o;
            o.x = acc[i][0] + bias.x;
            o.y = acc[i][1] + bias.y;
            o.z = acc[i][2] + bias.z;
            o.w = acc[i][3] + bias.w;
            if (RELU) {
                o.x = fmaxf(o.x, 0.f); o.y = fmaxf(o.y, 0.f);
                o.z = fmaxf(o.z, 0.f); o.w = fmaxf(o.w, 0.f);
            }
            *reinterpret_cast<float4*>(&OUT[(size_t)n * DD + tx * 4]) = o;
        }
    }
}

// ---------------- fused MLP + pred (float4 staging) ----------------
// h1 = relu( relu(EMB) @ Wm1 + bm1 );  PRED[n] = h1[n] . Wm2 + bm2
#define M_BM 32
#define M_BK 32
__global__ __launch_bounds__(256)
void mlp_pred_kernel(const float* __restrict__ EMB,
                     const float* __restrict__ Wm1,
                     const float* __restrict__ bm1,
                     const float* __restrict__ Wm2,
                     const float* __restrict__ bm2,
                     float* __restrict__ PRED,
                     int N) {
    __shared__ __align__(16) float sA[M_BM][M_BK];
    __shared__ __align__(16) float sB[M_BK][256];
    __shared__ float sred[M_BM][65];

    const int tid = threadIdx.x;
    const int tx  = tid & 63;
    const int ty  = tid >> 6;
    const int bm  = blockIdx.x * M_BM;

    float acc[8][4];
#pragma unroll
    for (int i = 0; i < 8; i++)
#pragma unroll
        for (int j = 0; j < 4; j++) acc[i][j] = 0.f;

    for (int kc = 0; kc < DD; kc += M_BK) {
        // A: 32x32 = 256 float4s -> 1 per thread, relu applied vectorwise
        {
            int r = tid >> 3, q = (tid & 7) * 4;
            int n = bm + r;
            float4 v = make_float4(0.f, 0.f, 0.f, 0.f);
            if (n < N)
                v = *reinterpret_cast<const float4*>(EMB + (size_t)n * DD + kc + q);
            v.x = fmaxf(v.x, 0.f); v.y = fmaxf(v.y, 0.f);
            v.z = fmaxf(v.z, 0.f); v.w = fmaxf(v.w, 0.f);
            *reinterpret_cast<float4*>(&sA[r][q]) = v;
        }
        // B: 32x256 = 2048 float4s -> 8 per thread
#pragma unroll
        for (int i = 0; i < 8; i++) {
            int idx = tid + i * 256;
            int kk = idx >> 6, c = (idx & 63) * 4;
            *reinterpret_cast<float4*>(&sB[kk][c]) =
                *reinterpret_cast<const float4*>(Wm1 + (size_t)(kc + kk) * 256 + c);
        }
        __syncthreads();

#pragma unroll
        for (int kk = 0; kk < M_BK; kk++) {
            float4 b4 = *reinterpret_cast<const float4*>(&sB[kk][tx * 4]);
#pragma unroll
            for (int i = 0; i < 8; i++) {
                float a = sA[ty * 8 + i][kk];
                acc[i][0] += a * b4.x;
                acc[i][1] += a * b4.y;
                acc[i][2] += a * b4.z;
                acc[i][3] += a * b4.w;
            }
        }
        __syncthreads();
    }

    float4 bias = *reinterpret_cast<const float4*>(&bm1[tx * 4]);
    float4 w2   = *reinterpret_cast<const float4*>(&Wm2[tx * 4]);
#pragma unroll
    for (int i = 0; i < 8; i++) {
        float h0 = fmaxf(acc[i][0] + bias.x, 0.f);
        float h1 = fmaxf(acc[i][1] + bias.y, 0.f);
        float h2 = fmaxf(acc[i][2] + bias.z, 0.f);
        float h3 = fmaxf(acc[i][3] + bias.w, 0.f);
        sred[ty * 8 + i][tx] = h0 * w2.x + h1 * w2.y + h2 * w2.z + h3 * w2.w;
    }
    __syncthreads();

    if (tid < M_BM) {
        int n = bm + tid;
        if (n < N) {
            float s = 0.f;
#pragma unroll
            for (int j = 0; j < 64; j++) s += sred[tid][j];
            PRED[n] = s + bm2[0];
        }
    }
}

// ---------------- launcher ----------------
extern "C" void kernel_launch(void* const* d_in, const int* in_sizes, int n_in,
                              void* d_out, int out_size) {
    const float* x   = (const float*)d_in[0];
    const void*  ei  = d_in[1];
    const float* Wl0 = (const float*)d_in[2];
    const float* b0  = (const float*)d_in[3];
    const float* Wr0 = (const float*)d_in[4];
    const float* Wl1 = (const float*)d_in[5];
    const float* b1  = (const float*)d_in[6];
    const float* Wr1 = (const float*)d_in[7];
    const float* Wm1 = (const float*)d_in[8];
    const float* bm1 = (const float*)d_in[9];
    const float* Wm2 = (const float*)d_in[10];
    const float* bm2 = (const float*)d_in[11];

    const int N = in_sizes[0] / DD;
    const int E = in_sizes[1] / 2;

    float* out  = (float*)d_out;
    float* emb  = out;                       // [N,128]
    float* pred = out + (size_t)N * DD;      // [N,1]

    const int egrid = (E + 255) / 256;
    const int ngrid = (N + 255) / 256;
    const int nblk  = (N + 1023) / 1024;
    const int ggrid = (N + 7) / 8;
    const int sgrid = (N + S_BM - 1) / S_BM;
    const int mgrid = (N + M_BM - 1) / M_BM;

    detect_kernel<<<1, 32>>>((const int*)ei);

    // ---- CSR build (once; reused by both layers) ----
    zero_hist_kernel<<<ngrid, 256>>>(N);
    hist_kernel<<<egrid, 256>>>(ei, E);
    scan1_kernel<<<nblk, 1024>>>(N);
    scan2_kernel<<<1, 32>>>(nblk);
    scan3_kernel<<<ngrid, 256>>>(N, E);
    scatter_kernel<<<egrid, 256>>>(ei, E);

    // ---- layer 0 ----
    gather_agg_kernel<<<ggrid, 256>>>(x, N);
    sage_kernel<true><<<sgrid, 256>>>(x, Wl0, Wr0, b0, nullptr, N);   // OUT -> g_h

    // ---- layer 1 (emb -> d_out) ----
    gather_agg_kernel<<<ggrid, 256>>>(nullptr, N);
    sage_kernel<false><<<sgrid, 256>>>(nullptr, Wl1, Wr1, b1, emb, N);

    // ---- post-mp MLP + pred (fused) ----
    mlp_pred_kernel<<<mgrid, 256>>>(emb, Wm1, bm1, Wm2, bm2, pred, N);
}

// round 16
// speedup vs baseline: 1.1724x; 1.0309x over previous
#include <cuda_runtime.h>
#include <cuda_bf16.h>
#include <cstdint>

#define NN 100000
#define EE 1600000
#define DD 128
#define NBLK ((NN + 1023) / 1024)

// ---------------- scratch (device globals; no allocs allowed) ----------------
__device__ float g_msg[(size_t)NN * DD];     // mean-aggregated messages
__device__ float g_h  [(size_t)NN * DD];     // layer-0 activations
__device__ int   g_rowptr[NN + 1];
__device__ int   g_colidx[EE];
__device__ int   g_hist[NN];
__device__ int   g_bsum[NBLK];
__device__ int   g_ei_is64;

// ---------------- edge-index dtype detection ----------------
__global__ void detect_kernel(const int* __restrict__ ei_words) {
    if (threadIdx.x == 0 && blockIdx.x == 0) {
        int is64 = 1;
        for (int i = 1; i < 256; i += 2) {
            if (ei_words[i] != 0) { is64 = 0; break; }
        }
        g_ei_is64 = is64;
    }
}
__device__ __forceinline__ int load_edge(const void* ei, size_t idx) {
    if (g_ei_is64) return (int)((const long long*)ei)[idx];
    return ((const int*)ei)[idx];
}

// ---------------- CSR build ----------------
__global__ void zero_hist_kernel(int N) {
    int i = blockIdx.x * blockDim.x + threadIdx.x;
    if (i < N) g_hist[i] = 0;
}
__global__ void hist_kernel(const void* __restrict__ ei, int E) {
    int e = blockIdx.x * blockDim.x + threadIdx.x;
    if (e >= E) return;
    atomicAdd(&g_hist[load_edge(ei, (size_t)E + e)], 1);
}
__global__ __launch_bounds__(1024)
void scan1_kernel(int N) {
    __shared__ int s[1024];
    int gi = blockIdx.x * 1024 + threadIdx.x;
    int v = (gi < N) ? g_hist[gi] : 0;
    s[threadIdx.x] = v;
    __syncthreads();
    int x = v;
#pragma unroll
    for (int off = 1; off < 1024; off <<= 1) {
        int t = (threadIdx.x >= off) ? s[threadIdx.x - off] : 0;
        __syncthreads();
        x += t;
        s[threadIdx.x] = x;
        __syncthreads();
    }
    if (gi <= N) g_rowptr[gi] = x - v;
    if (threadIdx.x == 1023) g_bsum[blockIdx.x] = x;
}
__global__ void scan2_kernel(int nblk) {
    if (threadIdx.x == 0 && blockIdx.x == 0) {
        int run = 0;
        for (int b = 0; b < nblk; b++) { int t = g_bsum[b]; g_bsum[b] = run; run += t; }
    }
}
__global__ void scan3_kernel(int N, int E) {
    int i = blockIdx.x * blockDim.x + threadIdx.x;
    if (i < N) {
        g_rowptr[i] += g_bsum[i >> 10];
        g_hist[i] = 0;
    }
    if (i == 0) g_rowptr[N] = E;
}
__global__ void scatter_kernel(const void* __restrict__ ei, int E) {
    int e = blockIdx.x * blockDim.x + threadIdx.x;
    if (e >= E) return;
    int s = load_edge(ei, e);
    int d = load_edge(ei, (size_t)E + e);
    int p = g_rowptr[d] + atomicAdd(&g_hist[d], 1);
    g_colidx[p] = s;
}

// ---------------- gather aggregation: one warp per dst node ----------------
__global__ __launch_bounds__(256)
void gather_agg_kernel(const float* __restrict__ feat_in, int N) {
    const float* feat = feat_in ? feat_in : g_h;
    int node = (blockIdx.x * blockDim.x + threadIdx.x) >> 5;
    int lane = threadIdx.x & 31;
    if (node >= N) return;

    int beg = g_rowptr[node];
    int end = g_rowptr[node + 1];
    const float4* f4 = reinterpret_cast<const float4*>(feat);
    float4 acc = make_float4(0.f, 0.f, 0.f, 0.f);

    int e = beg;
    for (; e + 4 <= end; e += 4) {
        int s0 = g_colidx[e], s1 = g_colidx[e + 1], s2 = g_colidx[e + 2], s3 = g_colidx[e + 3];
        float4 a = f4[(size_t)s0 * 32 + lane];
        float4 b = f4[(size_t)s1 * 32 + lane];
        float4 c = f4[(size_t)s2 * 32 + lane];
        float4 d = f4[(size_t)s3 * 32 + lane];
        acc.x += (a.x + b.x) + (c.x + d.x);
        acc.y += (a.y + b.y) + (c.y + d.y);
        acc.z += (a.z + b.z) + (c.z + d.z);
        acc.w += (a.w + b.w) + (c.w + d.w);
    }
    for (; e < end; e++) {
        float4 a = f4[(size_t)g_colidx[e] * 32 + lane];
        acc.x += a.x; acc.y += a.y; acc.z += a.z; acc.w += a.w;
    }
    float r = 1.f / fmaxf((float)(end - beg), 1.f);
    acc.x *= r; acc.y *= r; acc.z *= r; acc.w *= r;
    reinterpret_cast<float4*>(g_msg)[(size_t)node * 32 + lane] = acc;
}

// ---------------- fused SAGE layer GEMM (BM=32, 128 threads, 3 CTAs/SM) ----------------
// OUT[n][c] = act( sum_k g_msg[n][k]*Wl[k][c] + X[n][k]*Wr[k][c] + B[c] )
// Inner loop and per-thread microtile identical to R15; only CTA shape changed.
#define S_BM 32
#define S_BK 16
template <bool RELU>
__global__ __launch_bounds__(128)
void sage_kernel(const float* __restrict__ X_in,
                 const float* __restrict__ Wl,
                 const float* __restrict__ Wr,
                 const float* __restrict__ B,
                 float* __restrict__ OUT_in,
                 int N) {
    const float* X = X_in ? X_in : g_h;
    float* OUT     = OUT_in ? OUT_in : g_h;

    __shared__ __align__(16) float sAx[S_BM][S_BK];
    __shared__ __align__(16) float sAm[S_BM][S_BK];
    __shared__ __align__(16) float sBl[S_BK][128];
    __shared__ __align__(16) float sBr[S_BK][128];

    const int tid = threadIdx.x;
    const int tx  = tid & 31;          // col group: cols tx*4..+3
    const int ty  = tid >> 5;          // row group 0..3: rows ty*8..+7
    const int bm  = blockIdx.x * S_BM;

    // A staging: 32 rows x 16 cols = 128 float4s -> 1 float4/thread/source
    const int a_r = tid >> 2;          // row 0..31
    const int a_q = (tid & 3) * 4;     // col 0,4,8,12
    // B staging: 16x128 = 512 float4s per matrix -> 4 float4/thread/matrix

    float acc[8][4];
#pragma unroll
    for (int i = 0; i < 8; i++)
#pragma unroll
        for (int j = 0; j < 4; j++) acc[i][j] = 0.f;

    for (int kc = 0; kc < DD; kc += S_BK) {
        // A tiles
        {
            int n = bm + a_r;
            float4 vx = make_float4(0.f, 0.f, 0.f, 0.f);
            float4 vm = vx;
            if (n < N) {
                vx = *reinterpret_cast<const float4*>(X + (size_t)n * DD + kc + a_q);
                vm = *reinterpret_cast<const float4*>(g_msg + (size_t)n * DD + kc + a_q);
            }
            *reinterpret_cast<float4*>(&sAx[a_r][a_q]) = vx;
            *reinterpret_cast<float4*>(&sAm[a_r][a_q]) = vm;
        }
        // B tiles: 4 float4 per matrix per thread
#pragma unroll
        for (int i = 0; i < 4; i++) {
            int idx = tid + i * 128;
            int kk = idx >> 5, c = (idx & 31) * 4;
            *reinterpret_cast<float4*>(&sBl[kk][c]) =
                *reinterpret_cast<const float4*>(Wl + (size_t)(kc + kk) * 128 + c);
            *reinterpret_cast<float4*>(&sBr[kk][c]) =
                *reinterpret_cast<const float4*>(Wr + (size_t)(kc + kk) * 128 + c);
        }
        __syncthreads();

#pragma unroll
        for (int kk = 0; kk < S_BK; kk++) {
            float4 bl = *reinterpret_cast<const float4*>(&sBl[kk][tx * 4]);
            float4 br = *reinterpret_cast<const float4*>(&sBr[kk][tx * 4]);
#pragma unroll
            for (int i = 0; i < 8; i++) {
                float am = sAm[ty * 8 + i][kk];
                float ax = sAx[ty * 8 + i][kk];
                acc[i][0] += am * bl.x + ax * br.x;
                acc[i][1] += am * bl.y + ax * br.y;
                acc[i][2] += am * bl.z + ax * br.z;
                acc[i][3] += am * bl.w + ax * br.w;
            }
        }
        __syncthreads();
    }

    float4 bias = *reinterpret_cast<const float4*>(&B[tx * 4]);
#pragma unroll
    for (int i = 0; i < 8; i++) {
        int n = bm + ty * 8 + i;
        if (n < N) {
            float4 o;
            o.x = acc[i][0] + bias.x;
            o.y = acc[i][1] + bias.y;
            o.z = acc[i][2] + bias.z;
            o.w = acc[i][3] + bias.w;
            if (RELU) {
                o.x = fmaxf(o.x, 0.f); o.y = fmaxf(o.y, 0.f);
                o.z = fmaxf(o.z, 0.f); o.w = fmaxf(o.w, 0.f);
            }
            *reinterpret_cast<float4*>(&OUT[(size_t)n * DD + tx * 4]) = o;
        }
    }
}

// ---------------- fused MLP + pred (float4 staging, unchanged from R15) ----------------
#define M_BM 32
#define M_BK 32
__global__ __launch_bounds__(256)
void mlp_pred_kernel(const float* __restrict__ EMB,
                     const float* __restrict__ Wm1,
                     const float* __restrict__ bm1,
                     const float* __restrict__ Wm2,
                     const float* __restrict__ bm2,
                     float* __restrict__ PRED,
                     int N) {
    __shared__ __align__(16) float sA[M_BM][M_BK];
    __shared__ __align__(16) float sB[M_BK][256];
    __shared__ float sred[M_BM][65];

    const int tid = threadIdx.x;
    const int tx  = tid & 63;
    const int ty  = tid >> 6;
    const int bm  = blockIdx.x * M_BM;

    float acc[8][4];
#pragma unroll
    for (int i = 0; i < 8; i++)
#pragma unroll
        for (int j = 0; j < 4; j++) acc[i][j] = 0.f;

    for (int kc = 0; kc < DD; kc += M_BK) {
        {
            int r = tid >> 3, q = (tid & 7) * 4;
            int n = bm + r;
            float4 v = make_float4(0.f, 0.f, 0.f, 0.f);
            if (n < N)
                v = *reinterpret_cast<const float4*>(EMB + (size_t)n * DD + kc + q);
            v.x = fmaxf(v.x, 0.f); v.y = fmaxf(v.y, 0.f);
            v.z = fmaxf(v.z, 0.f); v.w = fmaxf(v.w, 0.f);
            *reinterpret_cast<float4*>(&sA[r][q]) = v;
        }
#pragma unroll
        for (int i = 0; i < 8; i++) {
            int idx = tid + i * 256;
            int kk = idx >> 6, c = (idx & 63) * 4;
            *reinterpret_cast<float4*>(&sB[kk][c]) =
                *reinterpret_cast<const float4*>(Wm1 + (size_t)(kc + kk) * 256 + c);
        }
        __syncthreads();

#pragma unroll
        for (int kk = 0; kk < M_BK; kk++) {
            float4 b4 = *reinterpret_cast<const float4*>(&sB[kk][tx * 4]);
#pragma unroll
            for (int i = 0; i < 8; i++) {
                float a = sA[ty * 8 + i][kk];
                acc[i][0] += a * b4.x;
                acc[i][1] += a * b4.y;
                acc[i][2] += a * b4.z;
                acc[i][3] += a * b4.w;
            }
        }
        __syncthreads();
    }

    float4 bias = *reinterpret_cast<const float4*>(&bm1[tx * 4]);
    float4 w2   = *reinterpret_cast<const float4*>(&Wm2[tx * 4]);
#pragma unroll
    for (int i = 0; i < 8; i++) {
        float h0 = fmaxf(acc[i][0] + bias.x, 0.f);
        float h1 = fmaxf(acc[i][1] + bias.y, 0.f);
        float h2 = fmaxf(acc[i][2] + bias.z, 0.f);
        float h3 = fmaxf(acc[i][3] + bias.w, 0.f);
        sred[ty * 8 + i][tx] = h0 * w2.x + h1 * w2.y + h2 * w2.z + h3 * w2.w;
    }
    __syncthreads();

    if (tid < M_BM) {
        int n = bm + tid;
        if (n < N) {
            float s = 0.f;
#pragma unroll
            for (int j = 0; j < 64; j++) s += sred[tid][j];
            PRED[n] = s + bm2[0];
        }
    }
}

// ---------------- launcher ----------------
extern "C" void kernel_launch(void* const* d_in, const int* in_sizes, int n_in,
                              void* d_out, int out_size) {
    const float* x   = (const float*)d_in[0];
    const void*  ei  = d_in[1];
    const float* Wl0 = (const float*)d_in[2];
    const float* b0  = (const float*)d_in[3];
    const float* Wr0 = (const float*)d_in[4];
    const float* Wl1 = (const float*)d_in[5];
    const float* b1  = (const float*)d_in[6];
    const float* Wr1 = (const float*)d_in[7];
    const float* Wm1 = (const float*)d_in[8];
    const float* bm1 = (const float*)d_in[9];
    const float* Wm2 = (const float*)d_in[10];
    const float* bm2 = (const float*)d_in[11];

    const int N = in_sizes[0] / DD;
    const int E = in_sizes[1] / 2;

    float* out  = (float*)d_out;
    float* emb  = out;                       // [N,128]
    float* pred = out + (size_t)N * DD;      // [N,1]

    const int egrid = (E + 255) / 256;
    const int ngrid = (N + 255) / 256;
    const int nblk  = (N + 1023) / 1024;
    const int ggrid = (N + 7) / 8;
    const int sgrid = (N + S_BM - 1) / S_BM;
    const int mgrid = (N + M_BM - 1) / M_BM;

    detect_kernel<<<1, 32>>>((const int*)ei);

    // ---- CSR build (once; reused by both layers) ----
    zero_hist_kernel<<<ngrid, 256>>>(N);
    hist_kernel<<<egrid, 256>>>(ei, E);
    scan1_kernel<<<nblk, 1024>>>(N);
    scan2_kernel<<<1, 32>>>(nblk);
    scan3_kernel<<<ngrid, 256>>>(N, E);
    scatter_kernel<<<egrid, 256>>>(ei, E);

    // ---- layer 0 ----
    gather_agg_kernel<<<ggrid, 256>>>(x, N);
    sage_kernel<true><<<sgrid, 128>>>(x, Wl0, Wr0, b0, nullptr, N);   // OUT -> g_h

    // ---- layer 1 (emb -> d_out) ----
    gather_agg_kernel<<<ggrid, 256>>>(nullptr, N);
    sage_kernel<false><<<sgrid, 128>>>(nullptr, Wl1, Wr1, b1, emb, N);

    // ---- post-mp MLP + pred (fused) ----
    mlp_pred_kernel<<<mgrid, 256>>>(emb, Wm1, bm1, Wm2, bm2, pred, N);
}

// round 17
// speedup vs baseline: 1.2173x; 1.0383x over previous
#include <cuda_runtime.h>
#include <cuda_bf16.h>
#include <cstdint>

#define NN 100000
#define EE 1600000
#define DD 128
#define NBLK ((NN + 1023) / 1024)

// ---------------- scratch (device globals; no allocs allowed) ----------------
__device__ float g_msg[(size_t)NN * DD];     // mean-aggregated messages
__device__ float g_h  [(size_t)NN * DD];     // layer-0 activations
__device__ int   g_rowptr[NN + 1];
__device__ int   g_colidx[EE];
__device__ int   g_hist[NN];
__device__ int   g_bsum[NBLK];
__device__ int   g_ei_is64;

// ---------------- cp.async helpers ----------------
__device__ __forceinline__ uint32_t smem_u32(const void* p) {
    uint32_t a;
    asm("{ .reg .u64 t; cvta.to.shared.u64 t, %1; cvt.u32.u64 %0, t; }" : "=r"(a) : "l"(p));
    return a;
}
__device__ __forceinline__ void cp_async16(uint32_t dst, const void* src, int srcsize) {
    asm volatile("cp.async.cg.shared.global [%0], [%1], 16, %2;"
                 :: "r"(dst), "l"(src), "r"(srcsize));
}
#define CP_COMMIT() asm volatile("cp.async.commit_group;" ::: "memory")
#define CP_WAIT(n)  asm volatile("cp.async.wait_group %0;" :: "n"(n) : "memory")

// ---------------- edge-index dtype detection ----------------
__global__ void detect_kernel(const int* __restrict__ ei_words) {
    if (threadIdx.x == 0 && blockIdx.x == 0) {
        int is64 = 1;
        for (int i = 1; i < 256; i += 2) {
            if (ei_words[i] != 0) { is64 = 0; break; }
        }
        g_ei_is64 = is64;
    }
}
__device__ __forceinline__ int load_edge(const void* ei, size_t idx) {
    if (g_ei_is64) return (int)((const long long*)ei)[idx];
    return ((const int*)ei)[idx];
}

// ---------------- CSR build ----------------
__global__ void zero_hist_kernel(int N) {
    int i = blockIdx.x * blockDim.x + threadIdx.x;
    if (i < N) g_hist[i] = 0;
}
__global__ void hist_kernel(const void* __restrict__ ei, int E) {
    int e = blockIdx.x * blockDim.x + threadIdx.x;
    if (e >= E) return;
    atomicAdd(&g_hist[load_edge(ei, (size_t)E + e)], 1);
}
__global__ __launch_bounds__(1024)
void scan1_kernel(int N) {
    __shared__ int s[1024];
    int gi = blockIdx.x * 1024 + threadIdx.x;
    int v = (gi < N) ? g_hist[gi] : 0;
    s[threadIdx.x] = v;
    __syncthreads();
    int x = v;
#pragma unroll
    for (int off = 1; off < 1024; off <<= 1) {
        int t = (threadIdx.x >= off) ? s[threadIdx.x - off] : 0;
        __syncthreads();
        x += t;
        s[threadIdx.x] = x;
        __syncthreads();
    }
    if (gi <= N) g_rowptr[gi] = x - v;
    if (threadIdx.x == 1023) g_bsum[blockIdx.x] = x;
}
__global__ void scan2_kernel(int nblk) {
    if (threadIdx.x == 0 && blockIdx.x == 0) {
        int run = 0;
        for (int b = 0; b < nblk; b++) { int t = g_bsum[b]; g_bsum[b] = run; run += t; }
    }
}
__global__ void scan3_kernel(int N, int E) {
    int i = blockIdx.x * blockDim.x + threadIdx.x;
    if (i < N) {
        g_rowptr[i] += g_bsum[i >> 10];
        g_hist[i] = 0;
    }
    if (i == 0) g_rowptr[N] = E;
}
__global__ void scatter_kernel(const void* __restrict__ ei, int E) {
    int e = blockIdx.x * blockDim.x + threadIdx.x;
    if (e >= E) return;
    int s = load_edge(ei, e);
    int d = load_edge(ei, (size_t)E + e);
    int p = g_rowptr[d] + atomicAdd(&g_hist[d], 1);
    g_colidx[p] = s;
}

// ---------------- gather aggregation: one warp per dst node ----------------
__global__ __launch_bounds__(256)
void gather_agg_kernel(const float* __restrict__ feat_in, int N) {
    const float* feat = feat_in ? feat_in : g_h;
    int node = (blockIdx.x * blockDim.x + threadIdx.x) >> 5;
    int lane = threadIdx.x & 31;
    if (node >= N) return;

    int beg = g_rowptr[node];
    int end = g_rowptr[node + 1];
    const float4* f4 = reinterpret_cast<const float4*>(feat);
    float4 acc = make_float4(0.f, 0.f, 0.f, 0.f);

    int e = beg;
    for (; e + 4 <= end; e += 4) {
        int s0 = g_colidx[e], s1 = g_colidx[e + 1], s2 = g_colidx[e + 2], s3 = g_colidx[e + 3];
        float4 a = f4[(size_t)s0 * 32 + lane];
        float4 b = f4[(size_t)s1 * 32 + lane];
        float4 c = f4[(size_t)s2 * 32 + lane];
        float4 d = f4[(size_t)s3 * 32 + lane];
        acc.x += (a.x + b.x) + (c.x + d.x);
        acc.y += (a.y + b.y) + (c.y + d.y);
        acc.z += (a.z + b.z) + (c.z + d.z);
        acc.w += (a.w + b.w) + (c.w + d.w);
    }
    for (; e < end; e++) {
        float4 a = f4[(size_t)g_colidx[e] * 32 + lane];
        acc.x += a.x; acc.y += a.y; acc.z += a.z; acc.w += a.w;
    }
    float r = 1.f / fmaxf((float)(end - beg), 1.f);
    acc.x *= r; acc.y *= r; acc.z *= r; acc.w *= r;
    reinterpret_cast<float4*>(g_msg)[(size_t)node * 32 + lane] = acc;
}

// ---------------- fused SAGE layer GEMM (BM=32, 128 thr, cp.async double-buffer) ----------------
// OUT[n][c] = act( sum_k g_msg[n][k]*Wl[k][c] + X[n][k]*Wr[k][c] + B[c] )
#define S_BM 32
#define S_BK 16
template <bool RELU>
__global__ __launch_bounds__(128)
void sage_kernel(const float* __restrict__ X_in,
                 const float* __restrict__ Wl,
                 const float* __restrict__ Wr,
                 const float* __restrict__ B,
                 float* __restrict__ OUT_in,
                 int N) {
    const float* X = X_in ? X_in : g_h;
    float* OUT     = OUT_in ? OUT_in : g_h;

    __shared__ __align__(16) float sAx[2][S_BM][S_BK];
    __shared__ __align__(16) float sAm[2][S_BM][S_BK];
    __shared__ __align__(16) float sBl[2][S_BK][128];
    __shared__ __align__(16) float sBr[2][S_BK][128];

    const int tid = threadIdx.x;
    const int tx  = tid & 31;          // col group: cols tx*4..+3
    const int ty  = tid >> 5;          // row group 0..3: rows ty*8..+7
    const int bm  = blockIdx.x * S_BM;

    // A staging: 1 float4/thread/source
    const int a_r = tid >> 2;
    const int a_q = (tid & 3) * 4;
    const int n_a  = bm + a_r;
    const bool va  = n_a < N;
    const int n_cl = va ? n_a : 0;
    const int a_sz = va ? 16 : 0;

    const uint32_t uAx0 = smem_u32(&sAx[0][a_r][a_q]);
    const uint32_t uAm0 = smem_u32(&sAm[0][a_r][a_q]);
    const uint32_t strideA = S_BM * S_BK * 4;   // 2048 B per stage
    const uint32_t strideB = S_BK * 128 * 4;    // 8192 B per stage

    // B staging dest addrs (4 float4 per matrix per thread)
    uint32_t uBl0[4], uBr0[4];
    int b_kk[4], b_c[4];
#pragma unroll
    for (int i = 0; i < 4; i++) {
        int idx = tid + i * 128;
        b_kk[i] = idx >> 5;
        b_c[i]  = (idx & 31) * 4;
        uBl0[i] = smem_u32(&sBl[0][b_kk[i]][b_c[i]]);
        uBr0[i] = smem_u32(&sBr[0][b_kk[i]][b_c[i]]);
    }

    float acc[8][4];
#pragma unroll
    for (int i = 0; i < 8; i++)
#pragma unroll
        for (int j = 0; j < 4; j++) acc[i][j] = 0.f;

    // ---- preload chunk 0 into stage 0 ----
    {
        cp_async16(uAx0, X + (size_t)n_cl * DD + a_q, a_sz);
        cp_async16(uAm0, g_msg + (size_t)n_cl * DD + a_q, a_sz);
#pragma unroll
        for (int i = 0; i < 4; i++) {
            cp_async16(uBl0[i], Wl + (size_t)b_kk[i] * 128 + b_c[i], 16);
            cp_async16(uBr0[i], Wr + (size_t)b_kk[i] * 128 + b_c[i], 16);
        }
        CP_COMMIT();
    }

    int stage = 0;
#pragma unroll 1
    for (int c = 0; c < DD / S_BK; c++) {
        const int kc = c * S_BK;
        const bool more = (c + 1 < DD / S_BK);
        if (more) {
            const int kn = kc + S_BK;
            const uint32_t so = (stage ^ 1) ? strideA : 0;
            const uint32_t sb = (stage ^ 1) ? strideB : 0;
            cp_async16(uAx0 + so, X + (size_t)n_cl * DD + kn + a_q, a_sz);
            cp_async16(uAm0 + so, g_msg + (size_t)n_cl * DD + kn + a_q, a_sz);
#pragma unroll
            for (int i = 0; i < 4; i++) {
                cp_async16(uBl0[i] + sb, Wl + (size_t)(kn + b_kk[i]) * 128 + b_c[i], 16);
                cp_async16(uBr0[i] + sb, Wr + (size_t)(kn + b_kk[i]) * 128 + b_c[i], 16);
            }
            CP_COMMIT();
            CP_WAIT(1);          // chunk c resident; chunk c+1 still in flight
        } else {
            CP_WAIT(0);
        }
        __syncthreads();

#pragma unroll
        for (int kk = 0; kk < S_BK; kk++) {
            float4 bl = *reinterpret_cast<const float4*>(&sBl[stage][kk][tx * 4]);
            float4 br = *reinterpret_cast<const float4*>(&sBr[stage][kk][tx * 4]);
#pragma unroll
            for (int i = 0; i < 8; i++) {
                float am = sAm[stage][ty * 8 + i][kk];
                float ax = sAx[stage][ty * 8 + i][kk];
                acc[i][0] += am * bl.x + ax * br.x;
                acc[i][1] += am * bl.y + ax * br.y;
                acc[i][2] += am * bl.z + ax * br.z;
                acc[i][3] += am * bl.w + ax * br.w;
            }
        }
        __syncthreads();
        stage ^= 1;
    }

    float4 bias = *reinterpret_cast<const float4*>(&B[tx * 4]);
#pragma unroll
    for (int i = 0; i < 8; i++) {
        int n = bm + ty * 8 + i;
        if (n < N) {
            float4 o;
            o.x = acc[i][0] + bias.x;
            o.y = acc[i][1] + bias.y;
            o.z = acc[i][2] + bias.z;
            o.w = acc[i][3] + bias.w;
            if (RELU) {
                o.x = fmaxf(o.x, 0.f); o.y = fmaxf(o.y, 0.f);
                o.z = fmaxf(o.z, 0.f); o.w = fmaxf(o.w, 0.f);
            }
            *reinterpret_cast<float4*>(&OUT[(size_t)n * DD + tx * 4]) = o;
        }
    }
}

// ---------------- fused MLP + pred (unchanged from R16) ----------------
#define M_BM 32
#define M_BK 32
__global__ __launch_bounds__(256)
void mlp_pred_kernel(const float* __restrict__ EMB,
                     const float* __restrict__ Wm1,
                     const float* __restrict__ bm1,
                     const float* __restrict__ Wm2,
                     const float* __restrict__ bm2,
                     float* __restrict__ PRED,
                     int N) {
    __shared__ __align__(16) float sA[M_BM][M_BK];
    __shared__ __align__(16) float sB[M_BK][256];
    __shared__ float sred[M_BM][65];

    const int tid = threadIdx.x;
    const int tx  = tid & 63;
    const int ty  = tid >> 6;
    const int bm  = blockIdx.x * M_BM;

    float acc[8][4];
#pragma unroll
    for (int i = 0; i < 8; i++)
#pragma unroll
        for (int j = 0; j < 4; j++) acc[i][j] = 0.f;

    for (int kc = 0; kc < DD; kc += M_BK) {
        {
            int r = tid >> 3, q = (tid & 7) * 4;
            int n = bm + r;
            float4 v = make_float4(0.f, 0.f, 0.f, 0.f);
            if (n < N)
                v = *reinterpret_cast<const float4*>(EMB + (size_t)n * DD + kc + q);
            v.x = fmaxf(v.x, 0.f); v.y = fmaxf(v.y, 0.f);
            v.z = fmaxf(v.z, 0.f); v.w = fmaxf(v.w, 0.f);
            *reinterpret_cast<float4*>(&sA[r][q]) = v;
        }
#pragma unroll
        for (int i = 0; i < 8; i++) {
            int idx = tid + i * 256;
            int kk = idx >> 6, c = (idx & 63) * 4;
            *reinterpret_cast<float4*>(&sB[kk][c]) =
                *reinterpret_cast<const float4*>(Wm1 + (size_t)(kc + kk) * 256 + c);
        }
        __syncthreads();

#pragma unroll
        for (int kk = 0; kk < M_BK; kk++) {
            float4 b4 = *reinterpret_cast<const float4*>(&sB[kk][tx * 4]);
#pragma unroll
            for (int i = 0; i < 8; i++) {
                float a = sA[ty * 8 + i][kk];
                acc[i][0] += a * b4.x;
                acc[i][1] += a * b4.y;
                acc[i][2] += a * b4.z;
                acc[i][3] += a * b4.w;
            }
        }
        __syncthreads();
    }

    float4 bias = *reinterpret_cast<const float4*>(&bm1[tx * 4]);
    float4 w2   = *reinterpret_cast<const float4*>(&Wm2[tx * 4]);
#pragma unroll
    for (int i = 0; i < 8; i++) {
        float h0 = fmaxf(acc[i][0] + bias.x, 0.f);
        float h1 = fmaxf(acc[i][1] + bias.y, 0.f);
        float h2 = fmaxf(acc[i][2] + bias.z, 0.f);
        float h3 = fmaxf(acc[i][3] + bias.w, 0.f);
        sred[ty * 8 + i][tx] = h0 * w2.x + h1 * w2.y + h2 * w2.z + h3 * w2.w;
    }
    __syncthreads();

    if (tid < M_BM) {
        int n = bm + tid;
        if (n < N) {
            float s = 0.f;
#pragma unroll
            for (int j = 0; j < 64; j++) s += sred[tid][j];
            PRED[n] = s + bm2[0];
        }
    }
}

// ---------------- launcher ----------------
extern "C" void kernel_launch(void* const* d_in, const int* in_sizes, int n_in,
                              void* d_out, int out_size) {
    const float* x   = (const float*)d_in[0];
    const void*  ei  = d_in[1];
    const float* Wl0 = (const float*)d_in[2];
    const float* b0  = (const float*)d_in[3];
    const float* Wr0 = (const float*)d_in[4];
    const float* Wl1 = (const float*)d_in[5];
    const float* b1  = (const float*)d_in[6];
    const float* Wr1 = (const float*)d_in[7];
    const float* Wm1 = (const float*)d_in[8];
    const float* bm1 = (const float*)d_in[9];
    const float* Wm2 = (const float*)d_in[10];
    const float* bm2 = (const float*)d_in[11];

    const int N = in_sizes[0] / DD;
    const int E = in_sizes[1] / 2;

    float* out  = (float*)d_out;
    float* emb  = out;                       // [N,128]
    float* pred = out + (size_t)N * DD;      // [N,1]

    const int egrid = (E + 255) / 256;
    const int ngrid = (N + 255) / 256;
    const int nblk  = (N + 1023) / 1024;
    const int ggrid = (N + 7) / 8;
    const int sgrid = (N + S_BM - 1) / S_BM;
    const int mgrid = (N + M_BM - 1) / M_BM;

    detect_kernel<<<1, 32>>>((const int*)ei);

    // ---- CSR build (once; reused by both layers) ----
    zero_hist_kernel<<<ngrid, 256>>>(N);
    hist_kernel<<<egrid, 256>>>(ei, E);
    scan1_kernel<<<nblk, 1024>>>(N);
    scan2_kernel<<<1, 32>>>(nblk);
    scan3_kernel<<<ngrid, 256>>>(N, E);
    scatter_kernel<<<egrid, 256>>>(ei, E);

    // ---- layer 0 ----
    gather_agg_kernel<<<ggrid, 256>>>(x, N);
    sage_kernel<true><<<sgrid, 128>>>(x, Wl0, Wr0, b0, nullptr, N);   // OUT -> g_h

    // ---- layer 1 (emb -> d_out) ----
    gather_agg_kernel<<<ggrid, 256>>>(nullptr, N);
    sage_kernel<false><<<sgrid, 128>>>(nullptr, Wl1, Wr1, b1, emb, N);

    // ---- post-mp MLP + pred (fused) ----
    mlp_pred_kernel<<<mgrid, 256>>>(emb, Wm1, bm1, Wm2, bm2, pred, N);
}